// round 4
// baseline (speedup 1.0000x reference)
#include <cuda_runtime.h>
#include <cuda_fp8.h>
#include <cstdint>

#define HIDDEN 4096
#define NTOK   4096

// ---------------- scratch (device globals; no allocs allowed) ----------------
__device__ __align__(1024) unsigned char g_Aq[(size_t)NTOK * HIDDEN];   // fp8 activations [M,K]
__device__ __align__(1024) unsigned char g_Wt[(size_t)HIDDEN * HIDDEN]; // fp8 W^T [N,K]

// ---------------- helpers ----------------
__device__ __forceinline__ uint32_t smem_u32(const void* p) {
    uint32_t a;
    asm("{ .reg .u64 t; cvta.to.shared.u64 t, %1; cvt.u32.u64 %0, t; }" : "=r"(a) : "l"(p));
    return a;
}

__device__ __forceinline__ void cp16(uint32_t dst, const void* src) {
    asm volatile("cp.async.cg.shared.global [%0], [%1], 16;" :: "r"(dst), "l"(src));
}
#define CP_COMMIT() asm volatile("cp.async.commit_group;" ::: "memory")
#define CP_WAIT(n)  asm volatile("cp.async.wait_group %0;" :: "n"(n) : "memory")

__device__ __forceinline__ void ldsm4(uint32_t& r0, uint32_t& r1, uint32_t& r2, uint32_t& r3,
                                      uint32_t addr) {
    asm volatile("ldmatrix.sync.aligned.m8n8.x4.shared.b16 {%0,%1,%2,%3}, [%4];"
                 : "=r"(r0), "=r"(r1), "=r"(r2), "=r"(r3) : "r"(addr));
}

__device__ __forceinline__ void mma_e4m3(float* c, const uint32_t* a, const uint32_t* b) {
    asm volatile(
        "mma.sync.aligned.m16n8k32.row.col.f32.e4m3.e4m3.f32 "
        "{%0,%1,%2,%3}, {%4,%5,%6,%7}, {%8,%9}, {%0,%1,%2,%3};"
        : "+f"(c[0]), "+f"(c[1]), "+f"(c[2]), "+f"(c[3])
        : "r"(a[0]), "r"(a[1]), "r"(a[2]), "r"(a[3]), "r"(b[0]), "r"(b[1]));
}

// ---------------- kernel 1: silu(gate)*up -> /s -> e4m3 ----------------
__global__ void act_quant_kernel(const float* __restrict__ x,
                                 const float* __restrict__ wscale,
                                 unsigned char* __restrict__ aq) {
    int idx = blockIdx.x * blockDim.x + threadIdx.x;   // each handles 4 elems
    int row = idx >> 10;
    int c4  = idx & 1023;
    const float s = wscale[0];
    const float4 g = *(const float4*)(x + (size_t)row * (2 * HIDDEN) + c4 * 4);
    const float4 u = *(const float4*)(x + (size_t)row * (2 * HIDDEN) + HIDDEN + c4 * 4);

    float gv[4] = {g.x, g.y, g.z, g.w};
    float uv[4] = {u.x, u.y, u.z, u.w};
    uint32_t packed = 0;
#pragma unroll
    for (int i = 0; i < 4; i++) {
        float sig = __fdividef(1.0f, 1.0f + __expf(-gv[i]));
        float y   = gv[i] * sig * uv[i];
        float q   = __fdiv_rn(y, s);
        __nv_fp8_storage_t b = __nv_cvt_float_to_fp8(q, __NV_SATFINITE, __NV_E4M3);
        packed |= ((uint32_t)b) << (i * 8);
    }
    *(uint32_t*)(aq + (size_t)idx * 4) = packed;
}

// ---------------- kernel 2: W [K,N] fp32 -> W^T [N,K] e4m3 ----------------
__global__ void w_quant_t_kernel(const float* __restrict__ w,
                                 unsigned char* __restrict__ wt) {
    __shared__ float tile[32][33];
    int n0 = blockIdx.x * 32;
    int k0 = blockIdx.y * 32;
    int tx = threadIdx.x, ty = threadIdx.y;  // (32, 8)
#pragma unroll
    for (int i = 0; i < 4; i++)
        tile[ty + i * 8][tx] = w[(size_t)(k0 + ty + i * 8) * HIDDEN + n0 + tx];
    __syncthreads();
#pragma unroll
    for (int i = 0; i < 4; i++) {
        float v = tile[tx][ty + i * 8];
        wt[(size_t)(n0 + ty + i * 8) * HIDDEN + k0 + tx] =
            (unsigned char)__nv_cvt_float_to_fp8(v, __NV_SATFINITE, __NV_E4M3);
    }
}

// ---------------- kernel 3: fp8 GEMM via mma.sync, D = Aq @ Wt^T, * s^2 ----------------
// 512 threads, 16 warps (2 m x 8 n), warp tile 64x32 -> 4x4 (m16n8) frags
static constexpr int BM = 128, BN = 256, BK = 64, STAGES = 4;
static constexpr int KT = HIDDEN / BK;            // 64
static constexpr int ROWB = 80;                   // 64 data + 16 pad (conflict-free ldmatrix)
static constexpr int A_ST = BM * ROWB;            // 10240
static constexpr int B_ST = BN * ROWB;            // 20480
static constexpr int STAGE_B = A_ST + B_ST;       // 30720
static constexpr int SMEM_TOTAL = STAGES * STAGE_B;  // 122880

__global__ void __launch_bounds__(512, 1) gemm_fp8_kernel(
    const unsigned char* __restrict__ A,   // [M,K] fp8
    const unsigned char* __restrict__ B,   // [N,K] fp8
    const float* __restrict__ wscale,
    float* __restrict__ out)
{
    extern __shared__ unsigned char smem[];
    const uint32_t sb = smem_u32(smem);
    const int tid  = threadIdx.x;
    const int lane = tid & 31;
    const int warp = tid >> 5;
    const int wm = warp >> 3;         // 0..1  (64 rows each)
    const int wn = warp & 7;          // 0..7  (32 cols each)
    const int m0 = blockIdx.x * BM;
    const int n0 = blockIdx.y * BN;

    // ---- stage loader: A 512 16B-chunks (1/thread), B 1024 (2/thread)
    auto load_stage = [&](int kt, int s) {
        const uint32_t st = sb + s * STAGE_B;
        const int kb = kt * BK;
        {
            int row = tid >> 2, ci = tid & 3;
            cp16(st + row * ROWB + ci * 16,
                 A + (size_t)(m0 + row) * HIDDEN + kb + ci * 16);
        }
#pragma unroll
        for (int it = 0; it < 2; it++) {
            int chunk = tid + it * 512;
            int row = chunk >> 2, ci = chunk & 3;
            cp16(st + A_ST + row * ROWB + ci * 16,
                 B + (size_t)(n0 + row) * HIDDEN + kb + ci * 16);
        }
    };

    float acc[4][4][4];
#pragma unroll
    for (int i = 0; i < 4; i++)
#pragma unroll
        for (int j = 0; j < 4; j++)
#pragma unroll
            for (int k = 0; k < 4; k++) acc[i][j][k] = 0.0f;

    // ldmatrix per-lane address components
    const int a_row = lane & 15;               // rows 0..15 within 16-row frag
    const int a_col = (lane >> 4) * 16;        // 0 or 16 (k halves)
    const int b_row = (lane & 7) + ((lane & 16) ? 8 : 0);   // n within 16-row pair
    const int b_col = (lane & 8) ? 16 : 0;                  // k half

    // prologue
#pragma unroll
    for (int s = 0; s < STAGES - 1; s++) { load_stage(s, s); CP_COMMIT(); }

    for (int kt = 0; kt < KT; kt++) {
        CP_WAIT(STAGES - 2);
        __syncthreads();
        const int nk = kt + STAGES - 1;
        if (nk < KT) load_stage(nk, nk & (STAGES - 1));
        CP_COMMIT();

        const uint32_t sA = sb + (kt & (STAGES - 1)) * STAGE_B;
        const uint32_t sBm = sA + A_ST;
#pragma unroll
        for (int ks = 0; ks < 2; ks++) {
            uint32_t aF[4][4], bF[4][2];
#pragma unroll
            for (int fm = 0; fm < 4; fm++) {
                uint32_t addr = sA + (wm * 64 + fm * 16 + a_row) * ROWB + ks * 32 + a_col;
                ldsm4(aF[fm][0], aF[fm][1], aF[fm][2], aF[fm][3], addr);
            }
#pragma unroll
            for (int p = 0; p < 2; p++) {    // each x4 covers two n-frags
                uint32_t addr = sBm + (wn * 32 + p * 16 + b_row) * ROWB + ks * 32 + b_col;
                ldsm4(bF[2 * p][0], bF[2 * p][1], bF[2 * p + 1][0], bF[2 * p + 1][1], addr);
            }
#pragma unroll
            for (int fm = 0; fm < 4; fm++)
#pragma unroll
                for (int fn = 0; fn < 4; fn++)
                    mma_e4m3(acc[fm][fn], aF[fm], bF[fn]);
        }
    }

    // ---- epilogue: * s^2, direct STG
    const float s1 = wscale[0];
    const float s2 = s1 * s1;
#pragma unroll
    for (int fm = 0; fm < 4; fm++) {
        const int r0 = m0 + wm * 64 + fm * 16 + (lane >> 2);
#pragma unroll
        for (int fn = 0; fn < 4; fn++) {
            const int c = n0 + wn * 32 + fn * 8 + (lane & 3) * 2;
            float2 v0 = {acc[fm][fn][0] * s2, acc[fm][fn][1] * s2};
            float2 v1 = {acc[fm][fn][2] * s2, acc[fm][fn][3] * s2};
            *(float2*)(out + (size_t)r0 * HIDDEN + c) = v0;
            *(float2*)(out + (size_t)(r0 + 8) * HIDDEN + c) = v1;
        }
    }
}

// ---------------- host ----------------
extern "C" void kernel_launch(void* const* d_in, const int* in_sizes, int n_in,
                              void* d_out, int out_size) {
    const float* x  = (const float*)d_in[0];
    const float* w  = (const float*)d_in[1];
    const float* ws = (const float*)d_in[2];
    float* out = (float*)d_out;
    (void)in_sizes; (void)n_in; (void)out_size;

    void* pA = nullptr; void* pW = nullptr;
    cudaGetSymbolAddress(&pA, g_Aq);
    cudaGetSymbolAddress(&pW, g_Wt);

    // prepasses
    act_quant_kernel<<<(NTOK * HIDDEN / 4) / 256, 256>>>(x, ws, (unsigned char*)pA);
    w_quant_t_kernel<<<dim3(HIDDEN / 32, HIDDEN / 32), dim3(32, 8)>>>(w, (unsigned char*)pW);

    // GEMM
    static bool attr_set = false;
    if (!attr_set) {
        cudaFuncSetAttribute(gemm_fp8_kernel, cudaFuncAttributeMaxDynamicSharedMemorySize,
                             SMEM_TOTAL);
        attr_set = true;
    }
    gemm_fp8_kernel<<<dim3(NTOK / BM, HIDDEN / BN), 512, SMEM_TOTAL>>>(
        (const unsigned char*)pA, (const unsigned char*)pW, ws, out);
}

// round 5
// speedup vs baseline: 1.1311x; 1.1311x over previous
#include <cuda.h>
#include <cuda_runtime.h>
#include <cuda_fp8.h>
#include <cstdint>

#define HIDDEN 4096
#define NTOK   4096

// ---------------- scratch (device globals; no allocs allowed) ----------------
__device__ __align__(1024) unsigned char g_Aq[(size_t)NTOK * HIDDEN];   // fp8 activations [M,K]
__device__ __align__(1024) unsigned char g_Wt[(size_t)HIDDEN * HIDDEN]; // fp8 W^T [N,K]

// ---------------- helpers ----------------
__device__ __forceinline__ uint32_t smem_u32(const void* p) {
    uint32_t a;
    asm("{ .reg .u64 t; cvta.to.shared.u64 t, %1; cvt.u32.u64 %0, t; }" : "=r"(a) : "l"(p));
    return a;
}

#define MBAR_INIT(addr, cnt) \
    asm volatile("mbarrier.init.shared.b64 [%0], %1;" :: "r"(addr), "r"(cnt) : "memory")
#define MBAR_EXPECT_TX(addr, bytes) \
    asm volatile("mbarrier.arrive.expect_tx.shared.b64 _, [%0], %1;" :: "r"(addr), "r"(bytes) : "memory")

__device__ __forceinline__ void mbar_wait(uint32_t mbar, uint32_t parity) {
    asm volatile(
        "{\n\t.reg .pred P;\n\t"
        "WAIT_%=:\n\t"
        "mbarrier.try_wait.parity.acquire.cta.shared::cta.b64 P, [%0], %1, 0x989680;\n\t"
        "@P bra.uni DONE_%=;\n\t"
        "bra.uni WAIT_%=;\n\t"
        "DONE_%=:\n\t}"
        :: "r"(mbar), "r"(parity) : "memory");
}

__device__ __forceinline__ void tma_load_2d(uint32_t dst_smem, const CUtensorMap* tm,
                                            int cx, int cy, uint32_t mbar) {
    asm volatile(
        "cp.async.bulk.tensor.2d.shared::cta.global.tile.mbarrier::complete_tx::bytes "
        "[%0], [%1, {%2, %3}], [%4];"
        :: "r"(dst_smem), "l"(tm), "r"(cx), "r"(cy), "r"(mbar) : "memory");
}

__device__ __forceinline__ void ldsm4(uint32_t& r0, uint32_t& r1, uint32_t& r2, uint32_t& r3,
                                      uint32_t addr) {
    asm volatile("ldmatrix.sync.aligned.m8n8.x4.shared.b16 {%0,%1,%2,%3}, [%4];"
                 : "=r"(r0), "=r"(r1), "=r"(r2), "=r"(r3) : "r"(addr));
}

__device__ __forceinline__ void mma_e4m3(float* c, const uint32_t* a, const uint32_t* b) {
    asm volatile(
        "mma.sync.aligned.m16n8k32.row.col.f32.e4m3.e4m3.f32 "
        "{%0,%1,%2,%3}, {%4,%5,%6,%7}, {%8,%9}, {%0,%1,%2,%3};"
        : "+f"(c[0]), "+f"(c[1]), "+f"(c[2]), "+f"(c[3])
        : "r"(a[0]), "r"(a[1]), "r"(a[2]), "r"(a[3]), "r"(b[0]), "r"(b[1]));
}

// ---------------- kernel 1: silu(gate)*up -> /s -> e4m3 ----------------
__global__ void act_quant_kernel(const float* __restrict__ x,
                                 const float* __restrict__ wscale,
                                 unsigned char* __restrict__ aq) {
    int idx = blockIdx.x * blockDim.x + threadIdx.x;
    int row = idx >> 10;
    int c4  = idx & 1023;
    const float s = wscale[0];
    const float4 g = *(const float4*)(x + (size_t)row * (2 * HIDDEN) + c4 * 4);
    const float4 u = *(const float4*)(x + (size_t)row * (2 * HIDDEN) + HIDDEN + c4 * 4);

    float gv[4] = {g.x, g.y, g.z, g.w};
    float uv[4] = {u.x, u.y, u.z, u.w};
    uint32_t packed = 0;
#pragma unroll
    for (int i = 0; i < 4; i++) {
        float sig = __fdividef(1.0f, 1.0f + __expf(-gv[i]));
        float y   = gv[i] * sig * uv[i];
        float q   = __fdiv_rn(y, s);
        __nv_fp8_storage_t b = __nv_cvt_float_to_fp8(q, __NV_SATFINITE, __NV_E4M3);
        packed |= ((uint32_t)b) << (i * 8);
    }
    *(uint32_t*)(aq + (size_t)idx * 4) = packed;
}

// ---------------- kernel 2: W [K,N] fp32 -> W^T [N,K] e4m3 ----------------
__global__ void w_quant_t_kernel(const float* __restrict__ w,
                                 unsigned char* __restrict__ wt) {
    __shared__ float tile[32][33];
    int n0 = blockIdx.x * 32;
    int k0 = blockIdx.y * 32;
    int tx = threadIdx.x, ty = threadIdx.y;  // (32, 8)
#pragma unroll
    for (int i = 0; i < 4; i++)
        tile[ty + i * 8][tx] = w[(size_t)(k0 + ty + i * 8) * HIDDEN + n0 + tx];
    __syncthreads();
#pragma unroll
    for (int i = 0; i < 4; i++) {
        float v = tile[tx][ty + i * 8];
        wt[(size_t)(n0 + ty + i * 8) * HIDDEN + k0 + tx] =
            (unsigned char)__nv_cvt_float_to_fp8(v, __NV_SATFINITE, __NV_E4M3);
    }
}

// ---------------- kernel 3: fp8 GEMM, TMA loads + mma.sync ----------------
// 256 threads, 8 warps (2 m x 4 n), warp tile 64x64; BK=128 bytes (SW128 atoms)
static constexpr int BM = 128, BN = 256, BK = 128, STAGES = 3;
static constexpr int KT = HIDDEN / BK;              // 32
static constexpr int A_ST = BM * BK;                // 16384
static constexpr int B_ST = BN * BK;                // 32768
static constexpr int STAGE_B = A_ST + B_ST;         // 49152
static constexpr int SMEM_ALLOC = 1024 + STAGES * STAGE_B;  // align slack + stages

__global__ void __launch_bounds__(256, 1) gemm_fp8_kernel(
    const __grid_constant__ CUtensorMap tmA,
    const __grid_constant__ CUtensorMap tmB,
    const float* __restrict__ wscale,
    float* __restrict__ out)
{
    extern __shared__ unsigned char smem[];
    __shared__ __align__(8) uint64_t mbar_s[STAGES];
    const uint32_t sb = (smem_u32(smem) + 1023u) & ~1023u;   // 1024-aligned for SW128 TMA
    const uint32_t mb = smem_u32(mbar_s);
    const int tid  = threadIdx.x;
    const int lane = tid & 31;
    const int warp = tid >> 5;
    const int wm = warp >> 2;         // 0..1  (64 rows)
    const int wn = warp & 3;          // 0..3  (64 cols)
    const int m0 = blockIdx.x * BM;
    const int n0 = blockIdx.y * BN;

    if (tid == 0) {
#pragma unroll
        for (int s = 0; s < STAGES; s++) MBAR_INIT(mb + s * 8, 1);
    }
    __syncthreads();

    float acc[4][8][4];
#pragma unroll
    for (int i = 0; i < 4; i++)
#pragma unroll
        for (int j = 0; j < 8; j++)
#pragma unroll
            for (int k = 0; k < 4; k++) acc[i][j][k] = 0.0f;

    // ldmatrix per-lane components (+ static SW128 XOR per lane)
    const int a_row = lane & 15;
    const int a_col = (lane >> 4) * 16;
    const uint32_t sxA = (uint32_t)(a_row & 7) << 4;
    const int b_row = (lane & 7) + ((lane & 16) ? 8 : 0);
    const int b_col = (lane & 8) ? 16 : 0;
    const uint32_t sxB = (uint32_t)(lane & 7) << 4;

    // prologue: fill stages 0..STAGES-2
    if (tid == 0) {
#pragma unroll
        for (int s = 0; s < STAGES - 1; s++) {
            MBAR_EXPECT_TX(mb + s * 8, STAGE_B);
            tma_load_2d(sb + s * STAGE_B,        &tmA, s * BK, m0, mb + s * 8);
            tma_load_2d(sb + s * STAGE_B + A_ST, &tmB, s * BK, n0, mb + s * 8);
        }
    }

    for (int kt = 0; kt < KT; kt++) {
        const int s = kt % STAGES;
        // refill the slot consumed at kt-1 (sync'ed at end of previous iter)
        if (tid == 0) {
            const int nk = kt + STAGES - 1;
            if (nk < KT) {
                const int sl = nk % STAGES;
                MBAR_EXPECT_TX(mb + sl * 8, STAGE_B);
                tma_load_2d(sb + sl * STAGE_B,        &tmA, nk * BK, m0, mb + sl * 8);
                tma_load_2d(sb + sl * STAGE_B + A_ST, &tmB, nk * BK, n0, mb + sl * 8);
            }
        }
        mbar_wait(mb + s * 8, (uint32_t)((kt / STAGES) & 1));

        const uint32_t sA  = sb + s * STAGE_B;
        const uint32_t sBm = sA + A_ST;
#pragma unroll
        for (int ks = 0; ks < 4; ks++) {
            uint32_t aF[4][4], bF[8][2];
            const uint32_t ca = (uint32_t)(ks * 32 + a_col) ^ sxA;
            const uint32_t cb = (uint32_t)(ks * 32 + b_col) ^ sxB;
#pragma unroll
            for (int fm = 0; fm < 4; fm++) {
                uint32_t addr = sA + (uint32_t)(wm * 64 + fm * 16 + a_row) * BK + ca;
                ldsm4(aF[fm][0], aF[fm][1], aF[fm][2], aF[fm][3], addr);
            }
#pragma unroll
            for (int p = 0; p < 4; p++) {    // each x4 covers two n-frags
                uint32_t addr = sBm + (uint32_t)(wn * 64 + p * 16 + b_row) * BK + cb;
                ldsm4(bF[2 * p][0], bF[2 * p][1], bF[2 * p + 1][0], bF[2 * p + 1][1], addr);
            }
#pragma unroll
            for (int fm = 0; fm < 4; fm++)
#pragma unroll
                for (int fn = 0; fn < 8; fn++)
                    mma_e4m3(acc[fm][fn], aF[fm], bF[fn]);
        }
        __syncthreads();   // all warps done with slot s before its refill next iter
    }

    // ---- epilogue: * s^2, direct STG
    const float s1 = wscale[0];
    const float s2 = s1 * s1;
#pragma unroll
    for (int fm = 0; fm < 4; fm++) {
        const int r0 = m0 + wm * 64 + fm * 16 + (lane >> 2);
#pragma unroll
        for (int fn = 0; fn < 8; fn++) {
            const int c = n0 + wn * 64 + fn * 8 + (lane & 3) * 2;
            float2 v0 = {acc[fm][fn][0] * s2, acc[fm][fn][1] * s2};
            float2 v1 = {acc[fm][fn][2] * s2, acc[fm][fn][3] * s2};
            *(float2*)(out + (size_t)r0 * HIDDEN + c) = v0;
            *(float2*)(out + (size_t)(r0 + 8) * HIDDEN + c) = v1;
        }
    }
}

// ---------------- host ----------------
typedef CUresult (*PFN_encodeTiled)(
    CUtensorMap*, CUtensorMapDataType, cuuint32_t, void*,
    const cuuint64_t*, const cuuint64_t*, const cuuint32_t*, const cuuint32_t*,
    CUtensorMapInterleave, CUtensorMapSwizzle, CUtensorMapL2promotion,
    CUtensorMapFloatOOBfill);

extern "C" void kernel_launch(void* const* d_in, const int* in_sizes, int n_in,
                              void* d_out, int out_size) {
    const float* x  = (const float*)d_in[0];
    const float* w  = (const float*)d_in[1];
    const float* ws = (const float*)d_in[2];
    float* out = (float*)d_out;
    (void)in_sizes; (void)n_in; (void)out_size;

    void* pA = nullptr; void* pW = nullptr;
    cudaGetSymbolAddress(&pA, g_Aq);
    cudaGetSymbolAddress(&pW, g_Wt);

    PFN_encodeTiled encode = nullptr;
    {
        void* sym = nullptr;
        cudaDriverEntryPointQueryResult qres;
        cudaGetDriverEntryPoint("cuTensorMapEncodeTiled", &sym, cudaEnableDefault, &qres);
        encode = (PFN_encodeTiled)sym;
    }

    CUtensorMap tmA, tmB;
    {
        cuuint64_t dims[2]    = {(cuuint64_t)HIDDEN, (cuuint64_t)NTOK};  // K bytes, rows
        cuuint64_t strides[1] = {(cuuint64_t)HIDDEN};
        cuuint32_t es[2]      = {1, 1};
        cuuint32_t boxA[2]    = {BK, BM};
        encode(&tmA, CU_TENSOR_MAP_DATA_TYPE_UINT8, 2, pA, dims, strides, boxA, es,
               CU_TENSOR_MAP_INTERLEAVE_NONE, CU_TENSOR_MAP_SWIZZLE_128B,
               CU_TENSOR_MAP_L2_PROMOTION_L2_128B, CU_TENSOR_MAP_FLOAT_OOB_FILL_NONE);
        cuuint32_t boxB[2]    = {BK, BN};
        encode(&tmB, CU_TENSOR_MAP_DATA_TYPE_UINT8, 2, pW, dims, strides, boxB, es,
               CU_TENSOR_MAP_INTERLEAVE_NONE, CU_TENSOR_MAP_SWIZZLE_128B,
               CU_TENSOR_MAP_L2_PROMOTION_L2_128B, CU_TENSOR_MAP_FLOAT_OOB_FILL_NONE);
    }

    // prepasses
    act_quant_kernel<<<(NTOK * HIDDEN / 4) / 256, 256>>>(x, ws, (unsigned char*)pA);
    w_quant_t_kernel<<<dim3(HIDDEN / 32, HIDDEN / 32), dim3(32, 8)>>>(w, (unsigned char*)pW);

    // GEMM
    static bool attr_set = false;
    if (!attr_set) {
        cudaFuncSetAttribute(gemm_fp8_kernel, cudaFuncAttributeMaxDynamicSharedMemorySize,
                             SMEM_ALLOC);
        attr_set = true;
    }
    gemm_fp8_kernel<<<dim3(NTOK / BM, HIDDEN / BN), 256, SMEM_ALLOC>>>(tmA, tmB, ws, out);
}